// round 16
// baseline (speedup 1.0000x reference)
#include <cuda_runtime.h>
#include <cuda_fp16.h>
#include <cstdint>

// ============================================================================
// BSpline via warp-level mma.sync (HMMA).
//   out[b,o] = sum_{i,c} basis(x[b,i])[c] * cp[i,c,o]
//   = GEMM: A (rows x 768) * B (768 x 64), k = i*12 + c.
// R16 = R15 (arithmetic knots, SoA B) with warp tile M32xN32 at FULL 32
//   warps/SM: M_TILE=64, 4 warps/CTA (2M x 2N), 8 k-passes (A tile 13.3KB)
//   -> 8 CTA/SM. wf/MMA drops 3 -> 2; B-LDG instrs halve; single wave.
//   A single-buffered (regs<=64), B depth-1 double-buffered.
// ============================================================================

#define DIMS 64
#define KSTEPS 48          // 768 / 16
#define NPASS 8
#define KS_PASS 6          // ksteps per pass
#define M_TILE 64
#define THREADS 128

#define A_PITCH_B 208      // bytes per A row per pass (odd x 16B)
#define SMEM_TOTAL (M_TILE * A_PITCH_B + 16)     // 13328

// B fragments, SoA lane-contiguous uint4 (same as R15):
//   g_Bf3[ ((ks*2 + nb)*2 + q)*32 + lane ] =
//     { frag(nt=2q).lo, frag(nt=2q).hi, frag(nt=2q+1).lo, frag(nt=2q+1).hi }
__device__ uint4 g_Bf3[KSTEPS * 2 * 2 * 32];

static __device__ __forceinline__ uint32_t s2u(const void* p) {
    uint32_t a;
    asm("{ .reg .u64 t; cvta.to.shared.u64 t, %1; cvt.u32.u64 %0, t; }" : "=r"(a) : "l"(p));
    return a;
}

static __device__ __forceinline__ float4 ldg_cs_f4(const float* p) {
    float4 v;
    asm volatile("ld.global.cs.v4.f32 {%0,%1,%2,%3}, [%4];"
                 : "=f"(v.x), "=f"(v.y), "=f"(v.z), "=f"(v.w) : "l"(p));
    return v;
}

static __device__ __forceinline__ void stg_cs_f2(float* p, float a, float b) {
    asm volatile("st.global.cs.v2.f32 [%0], {%1,%2};" :: "l"(p), "f"(a), "f"(b) : "memory");
}

static __device__ __forceinline__ void ldsm_x4(uint32_t& r0, uint32_t& r1,
                                               uint32_t& r2, uint32_t& r3,
                                               uint32_t addr) {
    asm volatile("ldmatrix.sync.aligned.m8n8.x4.shared.b16 {%0,%1,%2,%3}, [%4];"
                 : "=r"(r0), "=r"(r1), "=r"(r2), "=r"(r3) : "r"(addr));
}

static __device__ __forceinline__ void mma16816(float& d0, float& d1, float& d2, float& d3,
                                                uint32_t a0, uint32_t a1, uint32_t a2, uint32_t a3,
                                                uint32_t b0, uint32_t b1) {
    asm("mma.sync.aligned.m16n8k16.row.col.f32.f16.f16.f32 "
        "{%0,%1,%2,%3}, {%4,%5,%6,%7}, {%8,%9}, {%0,%1,%2,%3};"
        : "+f"(d0), "+f"(d1), "+f"(d2), "+f"(d3)
        : "r"(a0), "r"(a1), "r"(a2), "r"(a3), "r"(b0), "r"(b1));
}

static __device__ __forceinline__ uint32_t packh2(float a, float b) {
    uint32_t r;
    asm("cvt.rn.f16x2.f32 %0, %2, %1;" : "=r"(r) : "f"(a), "f"(b));
    return r;
}

// ---------------------------------------------------------------------------
// Prep: cp fp32 (seen as [k][o], k = i*12+c) -> SoA fragment-ordered fp16.
// ---------------------------------------------------------------------------
__global__ void bspline_prep_kernel(const float* __restrict__ cp) {
    int tid = blockIdx.x * blockDim.x + threadIdx.x;
    if (tid < KSTEPS * 2 * 2 * 32) {
        int lane = tid & 31;
        int q  = (tid >> 5) & 1;
        int nb = (tid >> 6) & 1;
        int ks = tid >> 7;
        int kq = lane & 3;
        int k0 = ks * 16 + kq * 2;
        int nbase = nb * 32 + (lane >> 2);
        int nA = nbase + (2 * q) * 8;
        int nB = nbase + (2 * q + 1) * 8;
        uint4 v;
        v.x = packh2(cp[(k0 + 0) * 64 + nA], cp[(k0 + 1) * 64 + nA]);
        v.y = packh2(cp[(k0 + 8) * 64 + nA], cp[(k0 + 9) * 64 + nA]);
        v.z = packh2(cp[(k0 + 0) * 64 + nB], cp[(k0 + 1) * 64 + nB]);
        v.w = packh2(cp[(k0 + 8) * 64 + nB], cp[(k0 + 9) * 64 + nB]);
        g_Bf3[tid] = v;
    }
}

// ---------------------------------------------------------------------------
// Main kernel: one CTA = 64 rows, 4 warps = 2(M) x 2(N), warp tile M32xN32.
// K processed in 8 passes of 96 (i in [8p, 8p+8), ksteps [6p, 6p+6)).
// ---------------------------------------------------------------------------
__global__ __launch_bounds__(THREADS, 8)
void bspline_hmma_kernel(const float* __restrict__ x,
                         float* __restrict__ out,
                         int nrows)
{
    extern __shared__ char sm[];
    const uint32_t sb = s2u(sm);
    const int t = threadIdx.x;
    const int wid = t >> 5;
    const int lid = t & 31;
    const int row0 = blockIdx.x * M_TILE;

    // Warp-tile constants
    const int mbase = (wid >> 1) * 32;      // 0, 32
    const int nb    = wid & 1;              // N group -> nbase = nb*32
    const int lrow = (lid & 7) + ((lid >> 3) & 1) * 8;
    const int lcol = (lid >> 4) * 16;
    const uint32_t aAddr0 = sb + (uint32_t)(mbase + lrow) * A_PITCH_B + lcol;
    const uint32_t aAddr1 = aAddr0 + 16u * A_PITCH_B;
    const uint4* __restrict__ Bf = g_Bf3 + (size_t)(nb * 64 + lid);

    float acc[2][4][4];
    #pragma unroll
    for (int mt = 0; mt < 2; mt++)
        #pragma unroll
        for (int nt = 0; nt < 4; nt++)
            #pragma unroll
            for (int q = 0; q < 4; q++) acc[mt][nt][q] = 0.0f;

    #pragma unroll
    for (int pass = 0; pass < NPASS; pass++) {
        __syncthreads();   // A-tile WAR between passes

        // ------------- Build phase: i in [8*pass, 8*pass+8) -------------
        // 64 rows x 2 i-quads = 128 tasks, 1 per thread.
        {
            const int r = t >> 1;               // row in tile
            const int iql = t & 1;              // local i-quad (0..1)
            const int row = min(row0 + r, nrows - 1);

            const float4 xv = ldg_cs_f4(x + (size_t)row * DIMS + (pass * 2 + iql) * 4);
            const uint32_t wbase = sb + (uint32_t)r * A_PITCH_B + (uint32_t)iql * 96u;

            #pragma unroll
            for (int u = 0; u < 4; u++) {
                float xc = (u == 0) ? xv.x : (u == 1) ? xv.y : (u == 2) ? xv.z : xv.w;
                xc = fminf(fmaxf(xc, 0.0f), 1.0f);

                const int s9 = min(8, (int)(xc * 9.0f));
                const float sf = (float)s9;
                const float C9 = 1.0f / 9.0f;

                // Clamped-uniform knots: T[j+d] = clamp(s9+d, 0, 9) / 9
                const float Tj   = sf * C9;
                const float Tjp1 = (sf + 1.0f) * C9;
                const float Tjm1 = fmaxf(sf - 1.0f, 0.0f) * C9;
                const float Tjm2 = fmaxf(sf - 2.0f, 0.0f) * C9;
                const float Tjp2 = fminf(sf + 2.0f, 9.0f) * C9;
                const float Tjp3 = fminf(sf + 3.0f, 9.0f) * C9;

                const float l1 = xc - Tj,   r1 = Tjp1 - xc;
                const float l2 = xc - Tjm1, r2 = Tjp2 - xc;
                const float l3 = xc - Tjm2, r3 = Tjp3 - xc;

                // Reciprocal knot spans: only {9, 4.5, 3} occur.
                const float i2a = (s9 == 0) ? 9.0f : 4.5f;
                const float i2b = (s9 == 8) ? 9.0f : 4.5f;
                const float i3a = (s9 >= 2) ? 3.0f : ((s9 == 1) ? 4.5f : 9.0f);
                const float i3b = (s9 == 0 || s9 == 8) ? 4.5f : 3.0f;
                const float i3c = (s9 <= 6) ? 3.0f : ((s9 == 7) ? 4.5f : 9.0f);

                float N0, N1, N2, N3, tmp, sv;
                N0 = r1 * 9.0f; N1 = l1 * 9.0f;
                tmp = N0 * i2a;
                N0 = r1 * tmp; sv = l2 * tmp;
                tmp = N1 * i2b;
                N1 = fmaf(r2, tmp, sv); N2 = l1 * tmp;
                tmp = N0 * i3a;
                N0 = r1 * tmp; sv = l3 * tmp;
                tmp = N1 * i3b;
                N1 = fmaf(r2, tmp, sv); sv = l2 * tmp;
                tmp = N2 * i3c;
                N2 = fmaf(r3, tmp, sv); N3 = l1 * tmp;

                const uint64_t w64 = (uint64_t)packh2(N0, N1)
                                   | ((uint64_t)packh2(N2, N3) << 32);
                const int sl = s9 >> 2;
                const int rs = (s9 & 3) * 16;
                const uint64_t lo = w64 << rs;
                const uint64_t hi = rs ? (w64 >> (64 - rs)) : 0ULL;

                const uint64_t a0 = (sl == 0) ? lo : 0ULL;
                const uint64_t a1 = (sl == 1) ? lo : ((sl == 0) ? hi : 0ULL);
                const uint64_t a2 = (sl == 2) ? lo : ((sl == 1) ? hi : 0ULL);

                const uint32_t w = wbase + (uint32_t)u * 24u;
                asm volatile("st.shared.u64 [%0], %1;" :: "r"(w),      "l"(a0) : "memory");
                asm volatile("st.shared.u64 [%0], %1;" :: "r"(w + 8),  "l"(a1) : "memory");
                asm volatile("st.shared.u64 [%0], %1;" :: "r"(w + 16), "l"(a2) : "memory");
            }
        }
        __syncthreads();

        // ------------- MMA phase: ksteps [6*pass, 6*pass+6) -------------
        uint4 bb[2][2];
        const int ksg0 = pass * KS_PASS;
        bb[0][0] = __ldg(Bf + ksg0 * 128);
        bb[0][1] = __ldg(Bf + ksg0 * 128 + 32);

        #pragma unroll
        for (int ksl = 0; ksl < KS_PASS; ksl++) {
            const int cur = ksl & 1;
            const int nxt = cur ^ 1;

            // A: issue both LDSMs first (latency covered by B prefetch + MMAs
            // of other warps; 8 warps/SMSP resident).
            uint32_t a0[4], a1[4];
            ldsm_x4(a0[0], a0[1], a0[2], a0[3], aAddr0 + ksl * 32);
            ldsm_x4(a1[0], a1[1], a1[2], a1[3], aAddr1 + ksl * 32);

            if (ksl + 1 < KS_PASS) {
                const int bi = (ksg0 + ksl + 1) * 128;
                bb[nxt][0] = __ldg(Bf + bi);
                bb[nxt][1] = __ldg(Bf + bi + 32);
            }

            const uint32_t b0[4] = { bb[cur][0].x, bb[cur][0].z, bb[cur][1].x, bb[cur][1].z };
            const uint32_t b1[4] = { bb[cur][0].y, bb[cur][0].w, bb[cur][1].y, bb[cur][1].w };
            #pragma unroll
            for (int nt = 0; nt < 4; nt++) {
                mma16816(acc[0][nt][0], acc[0][nt][1], acc[0][nt][2], acc[0][nt][3],
                         a0[0], a0[1], a0[2], a0[3], b0[nt], b1[nt]);
                mma16816(acc[1][nt][0], acc[1][nt][1], acc[1][nt][2], acc[1][nt][3],
                         a1[0], a1[1], a1[2], a1[3], b0[nt], b1[nt]);
            }
        }
    }

    // ---------------- Epilogue: streaming float2 stores ----------------
    const int rquad = lid >> 2;
    const int npair = (lid & 3) * 2;
    #pragma unroll
    for (int mt = 0; mt < 2; mt++) {
        #pragma unroll
        for (int nt = 0; nt < 4; nt++) {
            const int col = nb * 32 + nt * 8 + npair;
            const int rA = row0 + mbase + mt * 16 + rquad;
            const int rB = rA + 8;
            if (rA < nrows)
                stg_cs_f2(out + (size_t)rA * DIMS + col, acc[mt][nt][0], acc[mt][nt][1]);
            if (rB < nrows)
                stg_cs_f2(out + (size_t)rB * DIMS + col, acc[mt][nt][2], acc[mt][nt][3]);
        }
    }
}

extern "C" void kernel_launch(void* const* d_in, const int* in_sizes, int n_in,
                              void* d_out, int out_size)
{
    const float* x  = (const float*)d_in[0];   // (65536, 64)
    const float* cp = (const float*)d_in[1];   // (64, 12, 64) == B[768][64]
    float* out = (float*)d_out;

    const int nrows = in_sizes[0] / DIMS;

    bspline_prep_kernel<<<(KSTEPS * 2 * 2 * 32 + 255) / 256, 256>>>(cp);

    cudaFuncSetAttribute(bspline_hmma_kernel,
                         cudaFuncAttributeMaxDynamicSharedMemorySize, SMEM_TOTAL);
    const int grid = (nrows + M_TILE - 1) / M_TILE;
    bspline_hmma_kernel<<<grid, THREADS, SMEM_TOTAL>>>(x, out, nrows);
}

// round 17
// speedup vs baseline: 1.2317x; 1.2317x over previous
#include <cuda_runtime.h>
#include <cuda_fp16.h>
#include <cstdint>

// ============================================================================
// BSpline via warp-level mma.sync (HMMA).
//   out[b,o] = sum_{i,c} basis(x[b,i])[c] * cp[i,c,o]
//   = GEMM: A (rows x 768) * B (768 x 64), k = i*12 + c.
// R17 = R15 (best, 39.4us: M16xN32, 4 k-passes, 4 CTA/SM, 32 warps/SM,
//   arithmetic knots, SoA B) + build-phase stores batched: the 4 windows a
//   thread writes are 96 contiguous 16B-aligned bytes, so buffer 12 u64 in
//   registers and emit 6 x st.shared.v4.b32 instead of 12 x st.shared.u64.
// ============================================================================

#define DIMS 64
#define KSTEPS 48          // 768 / 16
#define NPASS 4
#define KS_PASS 12         // ksteps per pass
#define M_TILE 64
#define THREADS 256

#define A_PITCH_B 400      // bytes per A row per pass (odd x 16B)
#define SMEM_TOTAL (M_TILE * A_PITCH_B + 16)     // 25616

// B fragments, SoA lane-contiguous uint4 (same as R15):
//   g_Bf3[ ((ks*2 + nb)*2 + q)*32 + lane ] =
//     { frag(nt=2q).lo, frag(nt=2q).hi, frag(nt=2q+1).lo, frag(nt=2q+1).hi }
__device__ uint4 g_Bf3[KSTEPS * 2 * 2 * 32];

static __device__ __forceinline__ uint32_t s2u(const void* p) {
    uint32_t a;
    asm("{ .reg .u64 t; cvta.to.shared.u64 t, %1; cvt.u32.u64 %0, t; }" : "=r"(a) : "l"(p));
    return a;
}

static __device__ __forceinline__ float4 ldg_cs_f4(const float* p) {
    float4 v;
    asm volatile("ld.global.cs.v4.f32 {%0,%1,%2,%3}, [%4];"
                 : "=f"(v.x), "=f"(v.y), "=f"(v.z), "=f"(v.w) : "l"(p));
    return v;
}

static __device__ __forceinline__ void stg_cs_f2(float* p, float a, float b) {
    asm volatile("st.global.cs.v2.f32 [%0], {%1,%2};" :: "l"(p), "f"(a), "f"(b) : "memory");
}

static __device__ __forceinline__ void ldsm_x4(uint32_t& r0, uint32_t& r1,
                                               uint32_t& r2, uint32_t& r3,
                                               uint32_t addr) {
    asm volatile("ldmatrix.sync.aligned.m8n8.x4.shared.b16 {%0,%1,%2,%3}, [%4];"
                 : "=r"(r0), "=r"(r1), "=r"(r2), "=r"(r3) : "r"(addr));
}

static __device__ __forceinline__ void mma16816(float& d0, float& d1, float& d2, float& d3,
                                                uint32_t a0, uint32_t a1, uint32_t a2, uint32_t a3,
                                                uint32_t b0, uint32_t b1) {
    asm("mma.sync.aligned.m16n8k16.row.col.f32.f16.f16.f32 "
        "{%0,%1,%2,%3}, {%4,%5,%6,%7}, {%8,%9}, {%0,%1,%2,%3};"
        : "+f"(d0), "+f"(d1), "+f"(d2), "+f"(d3)
        : "r"(a0), "r"(a1), "r"(a2), "r"(a3), "r"(b0), "r"(b1));
}

static __device__ __forceinline__ uint32_t packh2(float a, float b) {
    uint32_t r;
    asm("cvt.rn.f16x2.f32 %0, %2, %1;" : "=r"(r) : "f"(a), "f"(b));
    return r;
}

// ---------------------------------------------------------------------------
// Prep: cp fp32 (seen as [k][o], k = i*12+c) -> SoA fragment-ordered fp16.
// ---------------------------------------------------------------------------
__global__ void bspline_prep_kernel(const float* __restrict__ cp) {
    int tid = blockIdx.x * blockDim.x + threadIdx.x;
    if (tid < KSTEPS * 2 * 2 * 32) {
        int lane = tid & 31;
        int q  = (tid >> 5) & 1;
        int nb = (tid >> 6) & 1;
        int ks = tid >> 7;
        int kq = lane & 3;
        int k0 = ks * 16 + kq * 2;
        int nbase = nb * 32 + (lane >> 2);
        int nA = nbase + (2 * q) * 8;
        int nB = nbase + (2 * q + 1) * 8;
        uint4 v;
        v.x = packh2(cp[(k0 + 0) * 64 + nA], cp[(k0 + 1) * 64 + nA]);
        v.y = packh2(cp[(k0 + 8) * 64 + nA], cp[(k0 + 9) * 64 + nA]);
        v.z = packh2(cp[(k0 + 0) * 64 + nB], cp[(k0 + 1) * 64 + nB]);
        v.w = packh2(cp[(k0 + 8) * 64 + nB], cp[(k0 + 9) * 64 + nB]);
        g_Bf3[tid] = v;
    }
}

// ---------------------------------------------------------------------------
// Main kernel: one CTA = 64 rows, 8 warps = 4(M) x 2(N), warp tile M16xN32.
// K processed in 4 passes of 192 (i in [16p, 16p+16), ksteps [12p, 12p+12)).
// ---------------------------------------------------------------------------
__global__ __launch_bounds__(THREADS, 4)
void bspline_hmma_kernel(const float* __restrict__ x,
                         float* __restrict__ out,
                         int nrows)
{
    extern __shared__ char sm[];
    const uint32_t sb = s2u(sm);
    const int t = threadIdx.x;
    const int wid = t >> 5;
    const int lid = t & 31;
    const int row0 = blockIdx.x * M_TILE;

    // Warp-tile constants (stable across passes)
    const int mbase = (wid >> 1) * 16;      // 0,16,32,48
    const int nb    = wid & 1;              // N group -> nbase = nb*32
    const int lrow = (lid & 7) + ((lid >> 3) & 1) * 8;
    const int lcol = (lid >> 4) * 16;
    const uint32_t aAddr = sb + (uint32_t)(mbase + lrow) * A_PITCH_B + lcol;
    const uint4* __restrict__ Bf = g_Bf3 + (size_t)(nb * 64 + lid);

    float acc[4][4];
    #pragma unroll
    for (int nt = 0; nt < 4; nt++)
        #pragma unroll
        for (int q = 0; q < 4; q++) acc[nt][q] = 0.0f;

    #pragma unroll
    for (int pass = 0; pass < NPASS; pass++) {
        __syncthreads();   // A-tile WAR between passes

        // ------------- Build phase: i in [16*pass, 16*pass+16) -------------
        // 64 rows x 4 i-quads = 256 tasks, 1 per thread; 4 windows = 96B
        // contiguous -> buffer 12 u64 in regs, store as 6 STS.128.
        {
            const int r = t >> 2;               // row in tile
            const int iql = t & 3;              // local i-quad (0..3)
            const int row = min(row0 + r, nrows - 1);

            const float4 xv = ldg_cs_f4(x + (size_t)row * DIMS + (pass * 4 + iql) * 4);
            const uint32_t wbase = sb + (uint32_t)r * A_PITCH_B + (uint32_t)iql * 96u;

            uint64_t buf[12];

            #pragma unroll
            for (int u = 0; u < 4; u++) {
                float xc = (u == 0) ? xv.x : (u == 1) ? xv.y : (u == 2) ? xv.z : xv.w;
                xc = fminf(fmaxf(xc, 0.0f), 1.0f);

                const int s9 = min(8, (int)(xc * 9.0f));
                const float sf = (float)s9;
                const float C9 = 1.0f / 9.0f;

                // Clamped-uniform knots: T[j+d] = clamp(s9+d, 0, 9) / 9
                const float Tj   = sf * C9;
                const float Tjp1 = (sf + 1.0f) * C9;
                const float Tjm1 = fmaxf(sf - 1.0f, 0.0f) * C9;
                const float Tjm2 = fmaxf(sf - 2.0f, 0.0f) * C9;
                const float Tjp2 = fminf(sf + 2.0f, 9.0f) * C9;
                const float Tjp3 = fminf(sf + 3.0f, 9.0f) * C9;

                const float l1 = xc - Tj,   r1 = Tjp1 - xc;
                const float l2 = xc - Tjm1, r2 = Tjp2 - xc;
                const float l3 = xc - Tjm2, r3 = Tjp3 - xc;

                // Reciprocal knot spans: only {9, 4.5, 3} occur.
                const float i2a = (s9 == 0) ? 9.0f : 4.5f;
                const float i2b = (s9 == 8) ? 9.0f : 4.5f;
                const float i3a = (s9 >= 2) ? 3.0f : ((s9 == 1) ? 4.5f : 9.0f);
                const float i3b = (s9 == 0 || s9 == 8) ? 4.5f : 3.0f;
                const float i3c = (s9 <= 6) ? 3.0f : ((s9 == 7) ? 4.5f : 9.0f);

                float N0, N1, N2, N3, tmp, sv;
                N0 = r1 * 9.0f; N1 = l1 * 9.0f;
                tmp = N0 * i2a;
                N0 = r1 * tmp; sv = l2 * tmp;
                tmp = N1 * i2b;
                N1 = fmaf(r2, tmp, sv); N2 = l1 * tmp;
                tmp = N0 * i3a;
                N0 = r1 * tmp; sv = l3 * tmp;
                tmp = N1 * i3b;
                N1 = fmaf(r2, tmp, sv); sv = l2 * tmp;
                tmp = N2 * i3c;
                N2 = fmaf(r3, tmp, sv); N3 = l1 * tmp;

                const uint64_t w64 = (uint64_t)packh2(N0, N1)
                                   | ((uint64_t)packh2(N2, N3) << 32);
                const int sl = s9 >> 2;
                const int rs = (s9 & 3) * 16;
                const uint64_t lo = w64 << rs;
                const uint64_t hi = rs ? (w64 >> (64 - rs)) : 0ULL;

                buf[u * 3 + 0] = (sl == 0) ? lo : 0ULL;
                buf[u * 3 + 1] = (sl == 1) ? lo : ((sl == 0) ? hi : 0ULL);
                buf[u * 3 + 2] = (sl == 2) ? lo : ((sl == 1) ? hi : 0ULL);
            }

            #pragma unroll
            for (int j = 0; j < 6; j++) {
                asm volatile("st.shared.v2.u64 [%0], {%1, %2};"
                             :: "r"(wbase + (uint32_t)j * 16u),
                                "l"(buf[2 * j]), "l"(buf[2 * j + 1]) : "memory");
            }
        }
        __syncthreads();

        // ------------- MMA phase: ksteps [12*pass, 12*pass+12) -------------
        uint32_t a[2][4];
        uint4 bb[2][2];

        const int ksg0 = pass * KS_PASS;
        ldsm_x4(a[0][0], a[0][1], a[0][2], a[0][3], aAddr);
        bb[0][0] = __ldg(Bf + ksg0 * 128);
        bb[0][1] = __ldg(Bf + ksg0 * 128 + 32);

        #pragma unroll 4
        for (int ksl = 0; ksl < KS_PASS; ksl++) {
            const int cur = ksl & 1;
            const int nxt = cur ^ 1;
            if (ksl + 1 < KS_PASS) {
                ldsm_x4(a[nxt][0], a[nxt][1], a[nxt][2], a[nxt][3],
                        aAddr + (ksl + 1) * 32);
                const int bi = (ksg0 + ksl + 1) * 128;
                bb[nxt][0] = __ldg(Bf + bi);
                bb[nxt][1] = __ldg(Bf + bi + 32);
            }
            const uint32_t b0[4] = { bb[cur][0].x, bb[cur][0].z, bb[cur][1].x, bb[cur][1].z };
            const uint32_t b1[4] = { bb[cur][0].y, bb[cur][0].w, bb[cur][1].y, bb[cur][1].w };
            #pragma unroll
            for (int nt = 0; nt < 4; nt++)
                mma16816(acc[nt][0], acc[nt][1], acc[nt][2], acc[nt][3],
                         a[cur][0], a[cur][1], a[cur][2], a[cur][3],
                         b0[nt], b1[nt]);
        }
    }

    // ---------------- Epilogue: streaming float2 stores ----------------
    const int rquad = lid >> 2;
    const int npair = (lid & 3) * 2;
    #pragma unroll
    for (int nt = 0; nt < 4; nt++) {
        const int col = nb * 32 + nt * 8 + npair;
        const int rA = row0 + mbase + rquad;
        const int rB = rA + 8;
        if (rA < nrows)
            stg_cs_f2(out + (size_t)rA * DIMS + col, acc[nt][0], acc[nt][1]);
        if (rB < nrows)
            stg_cs_f2(out + (size_t)rB * DIMS + col, acc[nt][2], acc[nt][3]);
    }
}

extern "C" void kernel_launch(void* const* d_in, const int* in_sizes, int n_in,
                              void* d_out, int out_size)
{
    const float* x  = (const float*)d_in[0];   // (65536, 64)
    const float* cp = (const float*)d_in[1];   // (64, 12, 64) == B[768][64]
    float* out = (float*)d_out;

    const int nrows = in_sizes[0] / DIMS;

    bspline_prep_kernel<<<(KSTEPS * 2 * 2 * 32 + 255) / 256, 256>>>(cp);

    cudaFuncSetAttribute(bspline_hmma_kernel,
                         cudaFuncAttributeMaxDynamicSharedMemorySize, SMEM_TOTAL);
    const int grid = (nrows + M_TILE - 1) / M_TILE;
    bspline_hmma_kernel<<<grid, THREADS, SMEM_TOTAL>>>(x, out, nrows);
}